// round 14
// baseline (speedup 1.0000x reference)
#include <cuda_runtime.h>
#include <cstdint>

// CCSDS-123 lossless predictor, [Z=224, Y=512, X=512].
// 4 rows per 256-thread block; 8 floats/thread; 256-bit (v8) global ld/st.
// reconstructed == sample_representatives == clip(img) == img (exact identity),
// so planes 5/6 store the staged input directly.

#define ZB 224
#define YB 512
#define XB 512

static constexpr size_t PLANE = (size_t)ZB * YB * XB;   // 58,720,256

__device__ __forceinline__ void ldg_v8(const float* p, float v[8]) {
    uint32_t r[8];
    asm volatile("ld.global.v8.b32 {%0,%1,%2,%3,%4,%5,%6,%7}, [%8];"
        : "=r"(r[0]), "=r"(r[1]), "=r"(r[2]), "=r"(r[3]),
          "=r"(r[4]), "=r"(r[5]), "=r"(r[6]), "=r"(r[7])
        : "l"(p));
#pragma unroll
    for (int i = 0; i < 8; ++i) v[i] = __uint_as_float(r[i]);
}

__device__ __forceinline__ void ldg_cs_v8(const float* p, float v[8]) {
    uint32_t r[8];
    asm volatile("ld.global.cs.v8.b32 {%0,%1,%2,%3,%4,%5,%6,%7}, [%8];"
        : "=r"(r[0]), "=r"(r[1]), "=r"(r[2]), "=r"(r[3]),
          "=r"(r[4]), "=r"(r[5]), "=r"(r[6]), "=r"(r[7])
        : "l"(p));
#pragma unroll
    for (int i = 0; i < 8; ++i) v[i] = __uint_as_float(r[i]);
}

__device__ __forceinline__ void stg_cs_v8(float* p, const float v[8]) {
    asm volatile("st.global.cs.v8.b32 [%0], {%1,%2,%3,%4,%5,%6,%7,%8};"
        :: "l"(p),
           "r"(__float_as_uint(v[0])), "r"(__float_as_uint(v[1])),
           "r"(__float_as_uint(v[2])), "r"(__float_as_uint(v[3])),
           "r"(__float_as_uint(v[4])), "r"(__float_as_uint(v[5])),
           "r"(__float_as_uint(v[6])), "r"(__float_as_uint(v[7]))
        : "memory");
}

__global__ __launch_bounds__(256) void ccsds123_kernel(
    const float* __restrict__ img, float* __restrict__ out)
{
    const int b   = blockIdx.x;          // 224 * 128 blocks
    const int z   = b >> 7;              // / 128
    const int y0  = (b & 127) << 2;      // row quad
    const int tid = threadIdx.x;

    __shared__ float SC[4 * XB];   // center rows y0..y0+3
    __shared__ float SN[XB];       // north row  y0-1
    __shared__ float SP[4 * XB];   // prev band rows y0..y0+3

    const float* base  = img + ((size_t)z * YB + y0) * XB;
    const float* pbase = base - (size_t)YB * XB;     // valid iff z > 0

    // ── Stage (v8 loads; 256 threads x 8 floats = 4 rows) ──
    {
        float v[8];
        ldg_v8(base + tid * 8, v);
        ((float4*)SC)[tid * 2 + 0] = make_float4(v[0], v[1], v[2], v[3]);
        ((float4*)SC)[tid * 2 + 1] = make_float4(v[4], v[5], v[6], v[7]);

        if (z > 0) ldg_cs_v8(pbase + tid * 8, v);
        else
#pragma unroll
            for (int i = 0; i < 8; ++i) v[i] = 0.f;
        ((float4*)SP)[tid * 2 + 0] = make_float4(v[0], v[1], v[2], v[3]);
        ((float4*)SP)[tid * 2 + 1] = make_float4(v[4], v[5], v[6], v[7]);

        if (tid < 64) {
            if (y0 > 0) ldg_v8(base - XB + tid * 8, v);
            else
#pragma unroll
                for (int i = 0; i < 8; ++i) v[i] = 0.f;
            ((float4*)SN)[tid * 2 + 0] = make_float4(v[0], v[1], v[2], v[3]);
            ((float4*)SN)[tid * 2 + 1] = make_float4(v[4], v[5], v[6], v[7]);
        }
    }
    __syncthreads();

    const int q  = tid >> 6;                 // which of the four rows
    const int t  = tid & 63;
    const int x0 = t * 8;
    const int y  = y0 + q;

    const float* sc = SC + q * XB;                     // center s(z, y, :)
    const float* sn = q ? (SC + (q - 1) * XB) : SN;    // north  s(z, y-1, :)
    const float* sp = SP + q * XB;                     // prev   s(z-1, y, :)

    float pr[8], rs[8], mp[8], cv[8];

#pragma unroll
    for (int i = 0; i < 8; ++i) {
        const int x = x0 + i;
        const float Cv  = sc[x];
        const float Wv  = (x > 0)      ? sc[x - 1] : 0.f;
        const float Nv  = sn[x];
        const float NWv = (x > 0)      ? sn[x - 1] : 0.f;
        const float NEv = (x < XB - 1) ? sn[x + 1] : 0.f;

        // neighbor-oriented local sum with edge cases
        float sigma;
        if (y == 0)           sigma = (x == 0) ? 0.f : 4.f * Wv;   // top row
        else if (x == 0)      sigma = 2.f * (Nv + NEv);            // left col
        else if (x == XB - 1) sigma = Wv + NWv + 2.f * Nv;         // right col
        else                  sigma = Wv + NWv + Nv + NEv;         // interior

        const float spred = sigma * 0.25f;
        const float pb    = sp[x];

        float p = (z == 0) ? spred : 0.5f * (spred + pb);
        if (y == 0 && x == 0) p = (z == 0) ? 0.f : pb;             // origin

        const float r  = Cv - p;                   // residual (== quantized)
        const float qv = rintf(r);                 // half-to-even, matches jnp.round
        const float m  = (qv >= 0.f) ? (2.f * qv) : (-2.f * qv - 1.f); // zigzag

        pr[i] = p; rs[i] = r; mp[i] = m;
        cv[i] = Cv;   // reconstructed == sample_repr == clip(p + r) == Cv exactly
    }

    const size_t off = ((size_t)z * YB + y) * XB + (size_t)x0;
    stg_cs_v8(out + off,             pr);  // predictions
    stg_cs_v8(out + off + PLANE,     rs);  // residuals
    stg_cs_v8(out + off + 2 * PLANE, rs);  // quantized residuals
    stg_cs_v8(out + off + 3 * PLANE, mp);  // mapped indices
    stg_cs_v8(out + off + 4 * PLANE, cv);  // sample representatives
    stg_cs_v8(out + off + 5 * PLANE, cv);  // reconstructed
}

extern "C" void kernel_launch(void* const* d_in, const int* in_sizes, int n_in,
                              void* d_out, int out_size)
{
    const float* img = (const float*)d_in[0];
    float* out = (float*)d_out;
    ccsds123_kernel<<<ZB * (YB / 4), 256>>>(img, out);
}

// round 15
// speedup vs baseline: 1.0082x; 1.0082x over previous
#include <cuda_runtime.h>

// CCSDS-123 lossless predictor, [Z=224, Y=512, X=512]. FINAL (converged).
// 4 rows per 512-thread block, flat one-barrier structure, streaming stores.
// At the compulsory-byte floor (1.41 GB writes + 235 MB reads) at ~83% of
// spec HBM — measured machine ceiling for this 6:1 write:read mix.
// reconstructed == sample_representatives == clip(img) == img exactly
// (all values multiples of 1/8, |v| < 2^17, img in [0, 32767]).

#define ZB 224
#define YB 512
#define XB 512

static constexpr size_t PLANE = (size_t)ZB * YB * XB;   // 58,720,256

__global__ __launch_bounds__(512, 4) void ccsds123_kernel(
    const float* __restrict__ img, float* __restrict__ out)
{
    const int b   = blockIdx.x;          // 224 * 128 blocks
    const int z   = b >> 7;              // / 128
    const int y0  = (b & 127) << 2;      // row quad
    const int tid = threadIdx.x;

    __shared__ float SC[4 * XB];   // center rows y0..y0+3
    __shared__ float SN[XB];       // north row  y0-1
    __shared__ float SP[4 * XB];   // prev band rows y0..y0+3

    const float* base  = img + ((size_t)z * YB + y0) * XB;
    const float* pbase = base - (size_t)YB * XB;     // valid iff z > 0

    // Stage: 512 float4s cover the four center rows / four prev-band rows.
    ((float4*)SC)[tid] = ((const float4*)base)[tid];
    if (z > 0) {
        const float* p = (const float*)((const float4*)pbase + tid);
        float4 pv;
        pv.x = __ldcs(p + 0);
        pv.y = __ldcs(p + 1);
        pv.z = __ldcs(p + 2);
        pv.w = __ldcs(p + 3);
        ((float4*)SP)[tid] = pv;
    } else {
        ((float4*)SP)[tid] = make_float4(0.f, 0.f, 0.f, 0.f);
    }
    if (tid < 128)
        ((float4*)SN)[tid] = (y0 > 0) ? ((const float4*)(base - XB))[tid]
                                      : make_float4(0.f, 0.f, 0.f, 0.f);
    __syncthreads();

    const int q  = tid >> 7;                 // which of the four rows
    const int t  = tid & 127;
    const int x0 = t * 4;
    const int y  = y0 + q;

    const float* sc = SC + q * XB;                     // center s(z, y, :)
    const float* sn = q ? (SC + (q - 1) * XB) : SN;    // north  s(z, y-1, :)
    const float* sp = SP + q * XB;                     // prev   s(z-1, y, :)

    float pr[4], rs[4], mp[4], cv[4];

#pragma unroll
    for (int i = 0; i < 4; ++i) {
        const int x = x0 + i;
        const float Cv  = sc[x];
        const float Wv  = (x > 0)      ? sc[x - 1] : 0.f;
        const float Nv  = sn[x];
        const float NWv = (x > 0)      ? sn[x - 1] : 0.f;
        const float NEv = (x < XB - 1) ? sn[x + 1] : 0.f;

        // neighbor-oriented local sum with edge cases
        float sigma;
        if (y == 0)           sigma = (x == 0) ? 0.f : 4.f * Wv;   // top row
        else if (x == 0)      sigma = 2.f * (Nv + NEv);            // left col
        else if (x == XB - 1) sigma = Wv + NWv + 2.f * Nv;         // right col
        else                  sigma = Wv + NWv + Nv + NEv;         // interior

        const float spred = sigma * 0.25f;
        const float pb    = sp[x];

        float p = (z == 0) ? spred : 0.5f * (spred + pb);
        if (y == 0 && x == 0) p = (z == 0) ? 0.f : pb;             // origin

        const float r  = Cv - p;                   // residual (== quantized)
        const float qv = rintf(r);                 // half-to-even, matches jnp.round
        const float m  = (qv >= 0.f) ? (2.f * qv) : (-2.f * qv - 1.f); // zigzag

        pr[i] = p; rs[i] = r; mp[i] = m;
        cv[i] = Cv;   // reconstructed == sample_repr == clip(p + r) == Cv exactly
    }

    const size_t off = ((size_t)z * YB + y) * XB + (size_t)x0;
    const float4 v_p = make_float4(pr[0], pr[1], pr[2], pr[3]);
    const float4 v_r = make_float4(rs[0], rs[1], rs[2], rs[3]);
    const float4 v_m = make_float4(mp[0], mp[1], mp[2], mp[3]);
    const float4 v_c = make_float4(cv[0], cv[1], cv[2], cv[3]);

    __stcs((float4*)(out + off),             v_p);  // predictions
    __stcs((float4*)(out + off + PLANE),     v_r);  // residuals
    __stcs((float4*)(out + off + 2 * PLANE), v_r);  // quantized residuals
    __stcs((float4*)(out + off + 3 * PLANE), v_m);  // mapped indices
    __stcs((float4*)(out + off + 4 * PLANE), v_c);  // sample representatives
    __stcs((float4*)(out + off + 5 * PLANE), v_c);  // reconstructed
}

extern "C" void kernel_launch(void* const* d_in, const int* in_sizes, int n_in,
                              void* d_out, int out_size)
{
    const float* img = (const float*)d_in[0];
    float* out = (float*)d_out;
    ccsds123_kernel<<<ZB * (YB / 4), 512>>>(img, out);
}